// round 2
// baseline (speedup 1.0000x reference)
#include <cuda_runtime.h>
#include <math.h>
#include <stdint.h>

// ---------------- problem constants ----------------
#define N_IMG 4
#define CIN   512
#define HH    64
#define WW    64
#define NPOS  (HH*WW)            // 4096
#define NANCH 9
#define A_TOT (NPOS*NANCH)       // 36864
#define SORT_N 65536
#define PRE_NMS  3000
#define POST_NMS 300
#define NMS_WORDS 94             // ceil(3000/32)
#define NMS_THRESH 0.7f
#define MIN_SIZE 16.0f

// ---------------- d_out layout (floats), reference return order ----------------
#define SZ_LOCS   (N_IMG*A_TOT*4)            // 589824
#define OFF_LOCS  0
#define SZ_SCORES (N_IMG*A_TOT*2)            // 294912
#define OFF_SCORES (OFF_LOCS+SZ_LOCS)        // 589824
#define SZ_ROIS   (N_IMG*POST_NMS*4)         // 4800
#define OFF_ROIS  (OFF_SCORES+SZ_SCORES)     // 884736
#define SZ_RIDX   (N_IMG*POST_NMS)           // 1200
#define OFF_RIDX  (OFF_ROIS+SZ_ROIS)         // 889536
#define OFF_ANCHOR (OFF_RIDX+SZ_RIDX)        // 890736  (size 147456)

// ---------------- device scratch ----------------
__device__ float               g_hidden[N_IMG*CIN*NPOS];        // 33.5 MB
__device__ float4              g_rois_all[N_IMG*A_TOT];         // 2.36 MB
__device__ unsigned long long  g_keys[N_IMG*SORT_N];            // 2 MB
__device__ float4              g_boxes_top[N_IMG*PRE_NMS];      // 192 KB
__device__ float               g_scores_top[N_IMG*PRE_NMS];     // 48 KB
__device__ unsigned            g_mask[(size_t)N_IMG*PRE_NMS*NMS_WORDS]; // 4.5 MB

// =================================================================
// 3x3 conv + ReLU  (implicit GEMM, fp32)
// block: 256 thr, tile = 64 oc x (4 rows x 32 cols), CC=8 cin chunk
// =================================================================
#define CC_CONV 8
#define OCT 64
#define RT  4
#define CT  32

__global__ __launch_bounds__(256) void conv3x3_kernel(
    const float* __restrict__ x, const float* __restrict__ W1,
    const float* __restrict__ b1)
{
    __shared__ __align__(16) float Ws_s[CC_CONV*9*OCT];  // [cc][k][oc]
    __shared__ float Xs[CC_CONV][6][36];                 // rows+2, cols+2 (34 valid)

    const int tid = threadIdx.x;
    const int tx  = tid & 15;        // out-channel group (4 oc each)
    const int ty  = tid >> 4;        // spatial group (8 cols each)
    const int r   = ty >> 2;         // local row 0..3
    const int c0  = (ty & 3) * 8;    // local col base
    const int x0  = blockIdx.x * CT;
    const int y0  = blockIdx.y * RT;
    const int z   = blockIdx.z;
    const int img = z >> 3;
    const int oc0 = (z & 7) * OCT;

    float acc[4][8];
#pragma unroll
    for (int i = 0; i < 4; i++)
#pragma unroll
        for (int j = 0; j < 8; j++) acc[i][j] = 0.f;

    const float* xin = x + (size_t)img * CIN * NPOS;

    for (int cc0 = 0; cc0 < CIN; cc0 += CC_CONV) {
        // load weights: CC*9*64 = 4608 floats
        for (int idx = tid; idx < CC_CONV*9*OCT; idx += 256) {
            int cc  = idx / (9*OCT);
            int rem = idx - cc*9*OCT;
            int kk  = rem >> 6;
            int oc  = rem & 63;
            Ws_s[(cc*9+kk)*OCT + oc] =
                W1[(size_t)(oc0+oc)*CIN*9 + (size_t)(cc0+cc)*9 + kk];
        }
        // load input halo tile: CC x 6 x 34 (stride 36)
        for (int idx = tid; idx < CC_CONV*6*36; idx += 256) {
            int cc  = idx / 216;
            int rem = idx - cc*216;
            int ry  = rem / 36;
            int rx  = rem - ry*36;
            float v = 0.f;
            int gy = y0 + ry - 1;
            int gx = x0 + rx - 1;
            if (rx < 34 && gy >= 0 && gy < HH && gx >= 0 && gx < WW)
                v = xin[(size_t)(cc0+cc)*NPOS + gy*WW + gx];
            Xs[cc][ry][rx] = v;
        }
        __syncthreads();

#pragma unroll
        for (int cc = 0; cc < CC_CONV; cc++) {
#pragma unroll
            for (int kk = 0; kk < 9; kk++) {
                const int ky = kk / 3, kx = kk - ky*3;
                float4 wv = reinterpret_cast<const float4*>(Ws_s)[(cc*9+kk)*16 + tx];
                float xv[8];
#pragma unroll
                for (int j = 0; j < 8; j++) xv[j] = Xs[cc][r+ky][c0+kx+j];
#pragma unroll
                for (int j = 0; j < 8; j++) {
                    acc[0][j] += wv.x * xv[j];
                    acc[1][j] += wv.y * xv[j];
                    acc[2][j] += wv.z * xv[j];
                    acc[3][j] += wv.w * xv[j];
                }
            }
        }
        __syncthreads();
    }

#pragma unroll
    for (int i = 0; i < 4; i++) {
        int oc = oc0 + tx*4 + i;
        float bias = b1[oc];
#pragma unroll
        for (int j = 0; j < 8; j++) {
            float v = acc[i][j] + bias;
            v = v > 0.f ? v : 0.f;
            g_hidden[((size_t)img*CIN + oc)*NPOS + (y0+r)*WW + (x0+c0+j)] = v;
        }
    }
}

// =================================================================
// 1x1 convs (loc 36 + score 18 = 54 outputs) written directly into
// d_out in the reference's reshaped layout.
// =================================================================
#define NOUT 54
__global__ __launch_bounds__(128) void conv1x1_kernel(
    const float* __restrict__ Wl, const float* __restrict__ bl,
    const float* __restrict__ Ws, const float* __restrict__ bs,
    float* __restrict__ out)
{
    __shared__ float Wc[64][NOUT];
    const int tid = threadIdx.x;
    const int img = blockIdx.y;
    const int pos = blockIdx.x * 128 + tid;

    float acc[NOUT];
#pragma unroll
    for (int o = 0; o < NOUT; o++) acc[o] = 0.f;

    const float* hid = g_hidden + (size_t)img * CIN * NPOS;

    for (int c0 = 0; c0 < CIN; c0 += 64) {
        for (int idx = tid; idx < 64*NOUT; idx += 128) {
            int c = idx / NOUT;
            int o = idx - c*NOUT;
            Wc[c][o] = (o < 36) ? Wl[(size_t)o*CIN + c0 + c]
                                : Ws[(size_t)(o-36)*CIN + c0 + c];
        }
        __syncthreads();
#pragma unroll 4
        for (int c = 0; c < 64; c++) {
            float h = hid[(size_t)(c0+c)*NPOS + pos];
#pragma unroll
            for (int o = 0; o < NOUT; o++) acc[o] += h * Wc[c][o];
        }
        __syncthreads();
    }

    float* locout = out + OFF_LOCS + (size_t)img*A_TOT*4 + (size_t)pos*36;
#pragma unroll
    for (int o = 0; o < 36; o++) locout[o] = acc[o] + bl[o];
    float* scout = out + OFF_SCORES + (size_t)img*A_TOT*2 + (size_t)pos*18;
#pragma unroll
    for (int o = 0; o < 18; o++) scout[o] = acc[36+o] + bs[o];
}

// =================================================================
// anchor generation into d_out anchor region
// =================================================================
__global__ void anchor_kernel(float* __restrict__ out)
{
    int i = blockIdx.x * blockDim.x + threadIdx.x;
    if (i >= A_TOT) return;
    int a   = i % 9;
    int pos = i / 9;
    int y = pos / WW, x = pos % WW;
    int ri = a / 3, si = a % 3;
    double rr = (ri == 0) ? 0.5 : (ri == 1 ? 1.0 : 2.0);
    double ss = (si == 0) ? 8.0 : (si == 1 ? 16.0 : 32.0);
    double h = 16.0 * ss * sqrt(rr);
    double w = 16.0 * ss * sqrt(1.0 / rr);
    float ymin = (float)(8.0 - h*0.5);
    float xmin = (float)(8.0 - w*0.5);
    float ymax = (float)(8.0 + h*0.5);
    float xmax = (float)(8.0 + w*0.5);
    float sy = (float)y * 16.0f, sx = (float)x * 16.0f;
    reinterpret_cast<float4*>(out + OFF_ANCHOR)[i] =
        make_float4(sy + ymin, sx + xmin, sy + ymax, sx + xmax);
}

// =================================================================
// proposal: loc2bbox + clip + min-size filter + fg softmax + sort key
// =================================================================
__device__ __forceinline__ float read_dim(const void* p)
{
    int v = *(const int*)p;
    if (v > 0 && v < (1 << 20)) return (float)v;   // plausibly int32
    return *(const float*)p;                        // else float bits
}

__global__ void proposal_kernel(const float* __restrict__ out,
                                const void* __restrict__ p_ih,
                                const void* __restrict__ p_iw)
{
    int t = blockIdx.x * blockDim.x + threadIdx.x;
    int img = t >> 16;          // / 65536
    int i   = t & (SORT_N - 1);
    if (img >= N_IMG) return;
    if (i >= A_TOT) { g_keys[t] = ~0ULL; return; }

    const float4 anc = reinterpret_cast<const float4*>(out + OFF_ANCHOR)[i];
    const float* loc = out + OFF_LOCS + (size_t)img*A_TOT*4 + (size_t)i*4;
    const float l0 = loc[0], l1 = loc[1], l2 = loc[2], l3 = loc[3];
    const float* sc = out + OFF_SCORES + (size_t)img*A_TOT*2 + (size_t)i*2;
    const float s0 = sc[0], s1 = sc[1];

    float h  = anc.z - anc.x, w = anc.w - anc.y;
    float cy = anc.x + 0.5f*h, cx = anc.y + 0.5f*w;
    float ncy = l0*h + cy, ncx = l1*w + cx;
    float nh  = expf(l2)*h,  nw  = expf(l3)*w;

    float fh = read_dim(p_ih), fw = read_dim(p_iw);
    float y1 = fminf(fmaxf(ncy - 0.5f*nh, 0.f), fh);
    float x1 = fminf(fmaxf(ncx - 0.5f*nw, 0.f), fw);
    float y2 = fminf(fmaxf(ncy + 0.5f*nh, 0.f), fh);
    float x2 = fminf(fmaxf(ncx + 0.5f*nw, 0.f), fw);

    bool ok = ((y2 - y1) >= MIN_SIZE) && ((x2 - x1) >= MIN_SIZE);

    float m  = fmaxf(s0, s1);
    float e0 = expf(s0 - m), e1 = expf(s1 - m);
    float fg = e1 / (e0 + e1);
    float score = ok ? fg : -INFINITY;

    g_rois_all[(size_t)img*A_TOT + i] = make_float4(y1, x1, y2, x2);

    unsigned u    = __float_as_uint(score);
    unsigned mkey = u ^ ((u >> 31) ? 0xFFFFFFFFu : 0x80000000u);   // ascending map
    unsigned dkey = ~mkey;                                          // descending
    g_keys[(size_t)img*SORT_N + i] = ((unsigned long long)dkey << 32) | (unsigned)i;
}

// =================================================================
// bitonic sort, 64-bit keys, 65536 elems per image, 4 images
// =================================================================
#define CHUNK 2048
__global__ __launch_bounds__(1024) void bitonic_local(int kstart, int fullsort)
{
    __shared__ unsigned long long sk[CHUNK];
    const int chunk = blockIdx.x;                       // 0..127
    unsigned long long* K = g_keys + (size_t)chunk * CHUNK;
    const int gbase = (chunk & 31) * CHUNK;             // index within image
    const int tid = threadIdx.x;

    sk[tid]        = K[tid];
    sk[tid + 1024] = K[tid + 1024];
    __syncthreads();

    if (fullsort) {
        for (int k = 2; k <= CHUNK; k <<= 1) {
            for (int j = k >> 1; j > 0; j >>= 1) {
                int i   = ((tid & ~(j - 1)) << 1) | (tid & (j - 1));
                int ixj = i | j;
                bool up = (((gbase + i) & k) == 0);
                unsigned long long a = sk[i], b = sk[ixj];
                if ((a > b) == up) { sk[i] = b; sk[ixj] = a; }
                __syncthreads();
            }
        }
    } else {
        const int k = kstart;
        for (int j = 1024; j > 0; j >>= 1) {
            int i   = ((tid & ~(j - 1)) << 1) | (tid & (j - 1));
            int ixj = i | j;
            bool up = (((gbase + i) & k) == 0);
            unsigned long long a = sk[i], b = sk[ixj];
            if ((a > b) == up) { sk[i] = b; sk[ixj] = a; }
            __syncthreads();
        }
    }
    K[tid]        = sk[tid];
    K[tid + 1024] = sk[tid + 1024];
}

__global__ void bitonic_global_step(int k, int j)
{
    int t   = blockIdx.x * blockDim.x + threadIdx.x;   // 4 * 32768
    int img = t >> 15;
    int tt  = t & 32767;
    int i   = ((tt & ~(j - 1)) << 1) | (tt & (j - 1));
    int ixj = i | j;
    unsigned long long* K = g_keys + (size_t)img * SORT_N;
    unsigned long long a = K[i], b = K[ixj];
    bool up = ((i & k) == 0);
    if ((a > b) == up) { K[i] = b; K[ixj] = a; }
}

// =================================================================
// gather top-3000 boxes + scores
// =================================================================
__global__ void gather_kernel()
{
    int t = blockIdx.x * blockDim.x + threadIdx.x;
    if (t >= N_IMG * PRE_NMS) return;
    int img = t / PRE_NMS;
    int i   = t - img * PRE_NMS;
    unsigned long long key = g_keys[(size_t)img*SORT_N + i];
    unsigned idx = (unsigned)(key & 0xFFFFFFFFu);
    g_boxes_top[t] = g_rois_all[(size_t)img*A_TOT + idx];
    unsigned dkey = (unsigned)(key >> 32);
    unsigned mkey = ~dkey;
    unsigned u = (mkey & 0x80000000u) ? (mkey ^ 0x80000000u) : ~mkey;
    g_scores_top[t] = __uint_as_float(u);
}

// =================================================================
// NMS suppression bitmask (3000 x 3000, only j > i bits)
// =================================================================
__global__ __launch_bounds__(64) void mask_kernel()
{
    const int img  = blockIdx.z;
    const int rowb = blockIdx.y * 64;
    const int colb = blockIdx.x * 64;
    __shared__ float4 cb[64];
    const int t = threadIdx.x;
    int col0 = colb + t;
    cb[t] = (col0 < PRE_NMS) ? g_boxes_top[(size_t)img*PRE_NMS + col0]
                             : make_float4(0.f, 0.f, 0.f, 0.f);
    __syncthreads();

    int row = rowb + t;
    if (row >= PRE_NMS) return;
    float4 rb = g_boxes_top[(size_t)img*PRE_NMS + row];
    float ra = fmaxf(rb.z - rb.x, 0.f) * fmaxf(rb.w - rb.y, 0.f);

    unsigned w0 = 0, w1 = 0;
#pragma unroll 4
    for (int c = 0; c < 64; c++) {
        int col = colb + c;
        if (col >= PRE_NMS || col <= row) continue;
        float4 b = cb[c];
        float yy1 = fmaxf(rb.x, b.x), xx1 = fmaxf(rb.y, b.y);
        float yy2 = fminf(rb.z, b.z), xx2 = fminf(rb.w, b.w);
        float inter = fmaxf(yy2 - yy1, 0.f) * fmaxf(xx2 - xx1, 0.f);
        float ba = fmaxf(b.z - b.x, 0.f) * fmaxf(b.w - b.y, 0.f);
        float iou = inter / (ra + ba - inter + 1e-9f);
        if (iou > NMS_THRESH) {
            if (c < 32) w0 |= 1u << c; else w1 |= 1u << (c - 32);
        }
    }
    unsigned* mrow = g_mask + ((size_t)img*PRE_NMS + row) * NMS_WORDS;
    int wi = colb >> 5;
    mrow[wi] = w0;
    if (wi + 1 < NMS_WORDS) mrow[wi + 1] = w1;
}

// =================================================================
// zero rois region + write roi_indices
// =================================================================
__global__ void fill_kernel(float* __restrict__ out)
{
    int t = blockIdx.x * blockDim.x + threadIdx.x;
    if (t < SZ_ROIS) out[OFF_ROIS + t] = 0.f;
    else if (t < SZ_ROIS + SZ_RIDX) {
        int i = t - SZ_ROIS;
        out[OFF_RIDX + i] = (float)(i / POST_NMS);
    }
}

// =================================================================
// sequential greedy NMS scan (1 warp per image), write kept rois
// =================================================================
__global__ void scan_kernel(float* __restrict__ out)
{
    const int img  = blockIdx.x;
    const int lane = threadIdx.x;

    unsigned sup0, sup1, sup2;
    {
        unsigned v[3];
#pragma unroll
        for (int s = 0; s < 3; s++) {
            unsigned vv = 0;
            int w = s*32 + lane;
            for (int b = 0; b < 32; b++) {
                int i = w*32 + b;
                if (i < PRE_NMS && g_scores_top[(size_t)img*PRE_NMS + i] == -INFINITY)
                    vv |= 1u << b;
            }
            v[s] = vv;
        }
        sup0 = v[0]; sup1 = v[1]; sup2 = v[2];
    }

    int keep = 0;
    const unsigned* maskbase = g_mask + (size_t)img*PRE_NMS*NMS_WORDS;

    for (int i = 0; i < PRE_NMS; i++) {
        int w = i >> 5, b = i & 31;
        int slot = w >> 5, owner = w & 31;
        unsigned myw = (slot == 0) ? sup0 : (slot == 1 ? sup1 : sup2);
        unsigned word = __shfl_sync(0xFFFFFFFFu, myw, owner);
        if (!((word >> b) & 1u)) {
            if (keep < POST_NMS && lane == 0) {
                float4 bx = g_boxes_top[(size_t)img*PRE_NMS + i];
                float* o = out + OFF_ROIS + ((size_t)img*POST_NMS + keep)*4;
                o[0] = bx.x; o[1] = bx.y; o[2] = bx.z; o[3] = bx.w;
            }
            keep++;
            const unsigned* mrow = maskbase + (size_t)i * NMS_WORDS;
            int w0i = lane, w1i = 32 + lane, w2i = 64 + lane;
            if (w0i < NMS_WORDS) sup0 |= mrow[w0i];
            if (w1i < NMS_WORDS) sup1 |= mrow[w1i];
            if (w2i < NMS_WORDS) sup2 |= mrow[w2i];
        }
    }
}

// =================================================================
// launch
// =================================================================
extern "C" void kernel_launch(void* const* d_in, const int* in_sizes, int n_in,
                              void* d_out, int out_size)
{
    const float* x   = (const float*)d_in[0];
    const void*  ih  = d_in[1];
    const void*  iw  = d_in[2];
    const float* W1  = (const float*)d_in[3];
    const float* b1  = (const float*)d_in[4];
    const float* Ws  = (const float*)d_in[5];
    const float* bs  = (const float*)d_in[6];
    const float* Wl  = (const float*)d_in[7];
    const float* bl  = (const float*)d_in[8];
    float* out = (float*)d_out;

    // 3x3 conv + relu
    conv3x3_kernel<<<dim3(WW/CT, HH/RT, N_IMG*8), 256>>>(x, W1, b1);
    // 1x1 heads -> d_out locs/scores
    conv1x1_kernel<<<dim3(NPOS/128, N_IMG), 128>>>(Wl, bl, Ws, bs, out);
    // anchors -> d_out anchor region
    anchor_kernel<<<(A_TOT + 255)/256, 256>>>(out);
    // zero rois + roi indices
    fill_kernel<<<(SZ_ROIS + SZ_RIDX + 255)/256, 256>>>(out);
    // proposals + sort keys
    proposal_kernel<<<(N_IMG*SORT_N)/256, 256>>>(out, ih, iw);

    // bitonic sort (descending score, ascending index ties)
    bitonic_local<<<128, 1024>>>(0, 1);
    for (int k = 4096; k <= SORT_N; k <<= 1) {
        for (int j = k >> 1; j >= CHUNK; j >>= 1)
            bitonic_global_step<<<(N_IMG*SORT_N/2)/256, 256>>>(k, j);
        bitonic_local<<<128, 1024>>>(k, 0);
    }

    // top-3000 gather
    gather_kernel<<<(N_IMG*PRE_NMS + 255)/256, 256>>>();
    // IoU bitmask
    mask_kernel<<<dim3(47, 47, N_IMG), 64>>>();
    // sequential NMS scan -> rois
    scan_kernel<<<N_IMG, 32>>>(out);
}

// round 3
// speedup vs baseline: 1.0009x; 1.0009x over previous
#include <cuda_runtime.h>
#include <math.h>
#include <stdint.h>

// ---------------- problem constants ----------------
#define N_IMG 4
#define CIN   512
#define HH    64
#define WW    64
#define NPOS  (HH*WW)            // 4096
#define NANCH 9
#define A_TOT (NPOS*NANCH)       // 36864
#define SORT_N 65536
#define PRE_NMS  3000
#define POST_NMS 300
#define NMS_WORDS 94             // ceil(3000/32)
#define NMS_THRESH 0.7f
#define MIN_SIZE 16.0f

// ---------------- d_out layout (floats), reference return order ----------------
#define SZ_LOCS   (N_IMG*A_TOT*4)            // 589824
#define OFF_LOCS  0
#define SZ_SCORES (N_IMG*A_TOT*2)            // 294912
#define OFF_SCORES (OFF_LOCS+SZ_LOCS)        // 589824
#define SZ_ROIS   (N_IMG*POST_NMS*4)         // 4800
#define OFF_ROIS  (OFF_SCORES+SZ_SCORES)     // 884736
#define SZ_RIDX   (N_IMG*POST_NMS)           // 1200
#define OFF_RIDX  (OFF_ROIS+SZ_ROIS)         // 889536
#define OFF_ANCHOR (OFF_RIDX+SZ_RIDX)        // 890736  (size 147456)

// ---------------- device scratch ----------------
__device__ float               g_hidden[N_IMG*CIN*NPOS];        // 33.5 MB
__device__ float4              g_rois_all[N_IMG*A_TOT];         // 2.36 MB
__device__ unsigned long long  g_keys[N_IMG*SORT_N];            // 2 MB
__device__ float4              g_boxes_top[N_IMG*PRE_NMS];      // 192 KB
__device__ float               g_scores_top[N_IMG*PRE_NMS];     // 48 KB
__device__ unsigned            g_mask[(size_t)N_IMG*PRE_NMS*NMS_WORDS]; // 4.5 MB

// =================================================================
// 3x3 conv + ReLU  (implicit GEMM, fp32)
// block: 256 thr, tile = 64 oc x (4 rows x 32 cols), CC=8 cin chunk
// =================================================================
#define CC_CONV 8
#define OCT 64
#define RT  4
#define CT  32

__global__ __launch_bounds__(256) void conv3x3_kernel(
    const float* __restrict__ x, const float* __restrict__ W1,
    const float* __restrict__ b1)
{
    __shared__ __align__(16) float Ws_s[CC_CONV*9*OCT];  // [cc][k][oc]
    __shared__ float Xs[CC_CONV][6][36];                 // rows+2, cols+2 (34 valid)

    const int tid = threadIdx.x;
    const int tx  = tid & 15;        // out-channel group (4 oc each)
    const int ty  = tid >> 4;        // spatial group (8 cols each)
    const int r   = ty >> 2;         // local row 0..3
    const int c0  = (ty & 3) * 8;    // local col base
    const int x0  = blockIdx.x * CT;
    const int y0  = blockIdx.y * RT;
    const int z   = blockIdx.z;
    const int img = z >> 3;
    const int oc0 = (z & 7) * OCT;

    float acc[4][8];
#pragma unroll
    for (int i = 0; i < 4; i++)
#pragma unroll
        for (int j = 0; j < 8; j++) acc[i][j] = 0.f;

    const float* xin = x + (size_t)img * CIN * NPOS;

    for (int cc0 = 0; cc0 < CIN; cc0 += CC_CONV) {
        // load weights: CC*9*64 = 4608 floats
        for (int idx = tid; idx < CC_CONV*9*OCT; idx += 256) {
            int cc  = idx / (9*OCT);
            int rem = idx - cc*9*OCT;
            int kk  = rem >> 6;
            int oc  = rem & 63;
            Ws_s[(cc*9+kk)*OCT + oc] =
                W1[(size_t)(oc0+oc)*CIN*9 + (size_t)(cc0+cc)*9 + kk];
        }
        // load input halo tile: CC x 6 x 34 (stride 36)
        for (int idx = tid; idx < CC_CONV*6*36; idx += 256) {
            int cc  = idx / 216;
            int rem = idx - cc*216;
            int ry  = rem / 36;
            int rx  = rem - ry*36;
            float v = 0.f;
            int gy = y0 + ry - 1;
            int gx = x0 + rx - 1;
            if (rx < 34 && gy >= 0 && gy < HH && gx >= 0 && gx < WW)
                v = xin[(size_t)(cc0+cc)*NPOS + gy*WW + gx];
            Xs[cc][ry][rx] = v;
        }
        __syncthreads();

#pragma unroll
        for (int cc = 0; cc < CC_CONV; cc++) {
#pragma unroll
            for (int kk = 0; kk < 9; kk++) {
                const int ky = kk / 3, kx = kk - ky*3;
                float4 wv = reinterpret_cast<const float4*>(Ws_s)[(cc*9+kk)*16 + tx];
                float xv[8];
#pragma unroll
                for (int j = 0; j < 8; j++) xv[j] = Xs[cc][r+ky][c0+kx+j];
#pragma unroll
                for (int j = 0; j < 8; j++) {
                    acc[0][j] += wv.x * xv[j];
                    acc[1][j] += wv.y * xv[j];
                    acc[2][j] += wv.z * xv[j];
                    acc[3][j] += wv.w * xv[j];
                }
            }
        }
        __syncthreads();
    }

#pragma unroll
    for (int i = 0; i < 4; i++) {
        int oc = oc0 + tx*4 + i;
        float bias = b1[oc];
#pragma unroll
        for (int j = 0; j < 8; j++) {
            float v = acc[i][j] + bias;
            v = v > 0.f ? v : 0.f;
            g_hidden[((size_t)img*CIN + oc)*NPOS + (y0+r)*WW + (x0+c0+j)] = v;
        }
    }
}

// =================================================================
// 1x1 convs (loc 36 + score 18 = 54 outputs) written directly into
// d_out in the reference's reshaped layout.
// =================================================================
#define NOUT 54
__global__ __launch_bounds__(128) void conv1x1_kernel(
    const float* __restrict__ Wl, const float* __restrict__ bl,
    const float* __restrict__ Ws, const float* __restrict__ bs,
    float* __restrict__ out)
{
    __shared__ float Wc[64][NOUT];
    const int tid = threadIdx.x;
    const int img = blockIdx.y;
    const int pos = blockIdx.x * 128 + tid;

    float acc[NOUT];
#pragma unroll
    for (int o = 0; o < NOUT; o++) acc[o] = 0.f;

    const float* hid = g_hidden + (size_t)img * CIN * NPOS;

    for (int c0 = 0; c0 < CIN; c0 += 64) {
        for (int idx = tid; idx < 64*NOUT; idx += 128) {
            int c = idx / NOUT;
            int o = idx - c*NOUT;
            Wc[c][o] = (o < 36) ? Wl[(size_t)o*CIN + c0 + c]
                                : Ws[(size_t)(o-36)*CIN + c0 + c];
        }
        __syncthreads();
#pragma unroll 4
        for (int c = 0; c < 64; c++) {
            float h = hid[(size_t)(c0+c)*NPOS + pos];
#pragma unroll
            for (int o = 0; o < NOUT; o++) acc[o] += h * Wc[c][o];
        }
        __syncthreads();
    }

    float* locout = out + OFF_LOCS + (size_t)img*A_TOT*4 + (size_t)pos*36;
#pragma unroll
    for (int o = 0; o < 36; o++) locout[o] = acc[o] + bl[o];
    float* scout = out + OFF_SCORES + (size_t)img*A_TOT*2 + (size_t)pos*18;
#pragma unroll
    for (int o = 0; o < 18; o++) scout[o] = acc[36+o] + bs[o];
}

// =================================================================
// anchor generation into d_out anchor region
// =================================================================
__global__ void anchor_kernel(float* __restrict__ out)
{
    int i = blockIdx.x * blockDim.x + threadIdx.x;
    if (i >= A_TOT) return;
    int a   = i % 9;
    int pos = i / 9;
    int y = pos / WW, x = pos % WW;
    int ri = a / 3, si = a % 3;
    double rr = (ri == 0) ? 0.5 : (ri == 1 ? 1.0 : 2.0);
    double ss = (si == 0) ? 8.0 : (si == 1 ? 16.0 : 32.0);
    double h = 16.0 * ss * sqrt(rr);
    double w = 16.0 * ss * sqrt(1.0 / rr);
    float ymin = (float)(8.0 - h*0.5);
    float xmin = (float)(8.0 - w*0.5);
    float ymax = (float)(8.0 + h*0.5);
    float xmax = (float)(8.0 + w*0.5);
    float sy = (float)y * 16.0f, sx = (float)x * 16.0f;
    reinterpret_cast<float4*>(out + OFF_ANCHOR)[i] =
        make_float4(sy + ymin, sx + xmin, sy + ymax, sx + xmax);
}

// =================================================================
// proposal: loc2bbox + clip + min-size filter + fg softmax + sort key
// =================================================================
__device__ __forceinline__ float read_dim(const void* p)
{
    int v = *(const int*)p;
    if (v > 0 && v < (1 << 20)) return (float)v;   // plausibly int32
    return *(const float*)p;                        // else float bits
}

__global__ void proposal_kernel(const float* __restrict__ out,
                                const void* __restrict__ p_ih,
                                const void* __restrict__ p_iw)
{
    int t = blockIdx.x * blockDim.x + threadIdx.x;
    int img = t >> 16;          // / 65536
    int i   = t & (SORT_N - 1);
    if (img >= N_IMG) return;
    if (i >= A_TOT) { g_keys[t] = ~0ULL; return; }

    const float4 anc = reinterpret_cast<const float4*>(out + OFF_ANCHOR)[i];
    const float* loc = out + OFF_LOCS + (size_t)img*A_TOT*4 + (size_t)i*4;
    const float l0 = loc[0], l1 = loc[1], l2 = loc[2], l3 = loc[3];
    const float* sc = out + OFF_SCORES + (size_t)img*A_TOT*2 + (size_t)i*2;
    const float s0 = sc[0], s1 = sc[1];

    float h  = anc.z - anc.x, w = anc.w - anc.y;
    float cy = anc.x + 0.5f*h, cx = anc.y + 0.5f*w;
    float ncy = l0*h + cy, ncx = l1*w + cx;
    float nh  = expf(l2)*h,  nw  = expf(l3)*w;

    float fh = read_dim(p_ih), fw = read_dim(p_iw);
    float y1 = fminf(fmaxf(ncy - 0.5f*nh, 0.f), fh);
    float x1 = fminf(fmaxf(ncx - 0.5f*nw, 0.f), fw);
    float y2 = fminf(fmaxf(ncy + 0.5f*nh, 0.f), fh);
    float x2 = fminf(fmaxf(ncx + 0.5f*nw, 0.f), fw);

    bool ok = ((y2 - y1) >= MIN_SIZE) && ((x2 - x1) >= MIN_SIZE);

    float m  = fmaxf(s0, s1);
    float e0 = expf(s0 - m), e1 = expf(s1 - m);
    float fg = e1 / (e0 + e1);
    float score = ok ? fg : -INFINITY;

    g_rois_all[(size_t)img*A_TOT + i] = make_float4(y1, x1, y2, x2);

    unsigned u    = __float_as_uint(score);
    unsigned mkey = u ^ ((u >> 31) ? 0xFFFFFFFFu : 0x80000000u);   // ascending map
    unsigned dkey = ~mkey;                                          // descending
    g_keys[(size_t)img*SORT_N + i] = ((unsigned long long)dkey << 32) | (unsigned)i;
}

// =================================================================
// bitonic sort, 64-bit keys, 65536 elems per image, 4 images
// =================================================================
#define CHUNK 2048
__global__ __launch_bounds__(1024) void bitonic_local(int kstart, int fullsort)
{
    __shared__ unsigned long long sk[CHUNK];
    const int chunk = blockIdx.x;                       // 0..127
    unsigned long long* K = g_keys + (size_t)chunk * CHUNK;
    const int gbase = (chunk & 31) * CHUNK;             // index within image
    const int tid = threadIdx.x;

    sk[tid]        = K[tid];
    sk[tid + 1024] = K[tid + 1024];
    __syncthreads();

    if (fullsort) {
        for (int k = 2; k <= CHUNK; k <<= 1) {
            for (int j = k >> 1; j > 0; j >>= 1) {
                int i   = ((tid & ~(j - 1)) << 1) | (tid & (j - 1));
                int ixj = i | j;
                bool up = (((gbase + i) & k) == 0);
                unsigned long long a = sk[i], b = sk[ixj];
                if ((a > b) == up) { sk[i] = b; sk[ixj] = a; }
                __syncthreads();
            }
        }
    } else {
        const int k = kstart;
        for (int j = 1024; j > 0; j >>= 1) {
            int i   = ((tid & ~(j - 1)) << 1) | (tid & (j - 1));
            int ixj = i | j;
            bool up = (((gbase + i) & k) == 0);
            unsigned long long a = sk[i], b = sk[ixj];
            if ((a > b) == up) { sk[i] = b; sk[ixj] = a; }
            __syncthreads();
        }
    }
    K[tid]        = sk[tid];
    K[tid + 1024] = sk[tid + 1024];
}

__global__ void bitonic_global_step(int k, int j)
{
    int t   = blockIdx.x * blockDim.x + threadIdx.x;   // 4 * 32768
    int img = t >> 15;
    int tt  = t & 32767;
    int i   = ((tt & ~(j - 1)) << 1) | (tt & (j - 1));
    int ixj = i | j;
    unsigned long long* K = g_keys + (size_t)img * SORT_N;
    unsigned long long a = K[i], b = K[ixj];
    bool up = ((i & k) == 0);
    if ((a > b) == up) { K[i] = b; K[ixj] = a; }
}

// =================================================================
// gather top-3000 boxes + scores
// =================================================================
__global__ void gather_kernel()
{
    int t = blockIdx.x * blockDim.x + threadIdx.x;
    if (t >= N_IMG * PRE_NMS) return;
    int img = t / PRE_NMS;
    int i   = t - img * PRE_NMS;
    unsigned long long key = g_keys[(size_t)img*SORT_N + i];
    unsigned idx = (unsigned)(key & 0xFFFFFFFFu);
    g_boxes_top[t] = g_rois_all[(size_t)img*A_TOT + idx];
    unsigned dkey = (unsigned)(key >> 32);
    unsigned mkey = ~dkey;
    unsigned u = (mkey & 0x80000000u) ? (mkey ^ 0x80000000u) : ~mkey;
    g_scores_top[t] = __uint_as_float(u);
}

// =================================================================
// NMS suppression bitmask (3000 x 3000, only j > i bits)
// =================================================================
__global__ __launch_bounds__(64) void mask_kernel()
{
    const int img  = blockIdx.z;
    const int rowb = blockIdx.y * 64;
    const int colb = blockIdx.x * 64;
    __shared__ float4 cb[64];
    const int t = threadIdx.x;
    int col0 = colb + t;
    cb[t] = (col0 < PRE_NMS) ? g_boxes_top[(size_t)img*PRE_NMS + col0]
                             : make_float4(0.f, 0.f, 0.f, 0.f);
    __syncthreads();

    int row = rowb + t;
    if (row >= PRE_NMS) return;
    float4 rb = g_boxes_top[(size_t)img*PRE_NMS + row];
    float ra = fmaxf(rb.z - rb.x, 0.f) * fmaxf(rb.w - rb.y, 0.f);

    unsigned w0 = 0, w1 = 0;
#pragma unroll 4
    for (int c = 0; c < 64; c++) {
        int col = colb + c;
        if (col >= PRE_NMS || col <= row) continue;
        float4 b = cb[c];
        float yy1 = fmaxf(rb.x, b.x), xx1 = fmaxf(rb.y, b.y);
        float yy2 = fminf(rb.z, b.z), xx2 = fminf(rb.w, b.w);
        float inter = fmaxf(yy2 - yy1, 0.f) * fmaxf(xx2 - xx1, 0.f);
        float ba = fmaxf(b.z - b.x, 0.f) * fmaxf(b.w - b.y, 0.f);
        float iou = inter / (ra + ba - inter + 1e-9f);
        if (iou > NMS_THRESH) {
            if (c < 32) w0 |= 1u << c; else w1 |= 1u << (c - 32);
        }
    }
    unsigned* mrow = g_mask + ((size_t)img*PRE_NMS + row) * NMS_WORDS;
    int wi = colb >> 5;
    mrow[wi] = w0;
    if (wi + 1 < NMS_WORDS) mrow[wi + 1] = w1;
}

// =================================================================
// zero rois region + write roi_indices
// =================================================================
__global__ void fill_kernel(float* __restrict__ out)
{
    int t = blockIdx.x * blockDim.x + threadIdx.x;
    if (t < SZ_ROIS) out[OFF_ROIS + t] = 0.f;
    else if (t < SZ_ROIS + SZ_RIDX) {
        int i = t - SZ_ROIS;
        out[OFF_RIDX + i] = (float)(i / POST_NMS);
    }
}

// =================================================================
// sequential greedy NMS scan (1 warp per image), write kept rois
// =================================================================
__global__ void scan_kernel(float* __restrict__ out)
{
    const int img  = blockIdx.x;
    const int lane = threadIdx.x;

    unsigned sup0, sup1, sup2;
    {
        unsigned v[3];
#pragma unroll
        for (int s = 0; s < 3; s++) {
            unsigned vv = 0;
            int w = s*32 + lane;
            for (int b = 0; b < 32; b++) {
                int i = w*32 + b;
                if (i < PRE_NMS && g_scores_top[(size_t)img*PRE_NMS + i] == -INFINITY)
                    vv |= 1u << b;
            }
            v[s] = vv;
        }
        sup0 = v[0]; sup1 = v[1]; sup2 = v[2];
    }

    int keep = 0;
    const unsigned* maskbase = g_mask + (size_t)img*PRE_NMS*NMS_WORDS;

    for (int i = 0; i < PRE_NMS; i++) {
        int w = i >> 5, b = i & 31;
        int slot = w >> 5, owner = w & 31;
        unsigned myw = (slot == 0) ? sup0 : (slot == 1 ? sup1 : sup2);
        unsigned word = __shfl_sync(0xFFFFFFFFu, myw, owner);
        if (!((word >> b) & 1u)) {
            if (keep < POST_NMS && lane == 0) {
                float4 bx = g_boxes_top[(size_t)img*PRE_NMS + i];
                float* o = out + OFF_ROIS + ((size_t)img*POST_NMS + keep)*4;
                o[0] = bx.x; o[1] = bx.y; o[2] = bx.z; o[3] = bx.w;
            }
            keep++;
            const unsigned* mrow = maskbase + (size_t)i * NMS_WORDS;
            int w0i = lane, w1i = 32 + lane, w2i = 64 + lane;
            if (w0i < NMS_WORDS) sup0 |= mrow[w0i];
            if (w1i < NMS_WORDS) sup1 |= mrow[w1i];
            if (w2i < NMS_WORDS) sup2 |= mrow[w2i];
        }
    }
}

// =================================================================
// launch
// =================================================================
extern "C" void kernel_launch(void* const* d_in, const int* in_sizes, int n_in,
                              void* d_out, int out_size)
{
    const float* x   = (const float*)d_in[0];
    const void*  ih  = d_in[1];
    const void*  iw  = d_in[2];
    const float* W1  = (const float*)d_in[3];
    const float* b1  = (const float*)d_in[4];
    const float* Ws  = (const float*)d_in[5];
    const float* bs  = (const float*)d_in[6];
    const float* Wl  = (const float*)d_in[7];
    const float* bl  = (const float*)d_in[8];
    float* out = (float*)d_out;

    // 3x3 conv + relu
    conv3x3_kernel<<<dim3(WW/CT, HH/RT, N_IMG*8), 256>>>(x, W1, b1);
    // 1x1 heads -> d_out locs/scores
    conv1x1_kernel<<<dim3(NPOS/128, N_IMG), 128>>>(Wl, bl, Ws, bs, out);
    // anchors -> d_out anchor region
    anchor_kernel<<<(A_TOT + 255)/256, 256>>>(out);
    // zero rois + roi indices
    fill_kernel<<<(SZ_ROIS + SZ_RIDX + 255)/256, 256>>>(out);
    // proposals + sort keys
    proposal_kernel<<<(N_IMG*SORT_N)/256, 256>>>(out, ih, iw);

    // bitonic sort (descending score, ascending index ties)
    bitonic_local<<<128, 1024>>>(0, 1);
    for (int k = 4096; k <= SORT_N; k <<= 1) {
        for (int j = k >> 1; j >= CHUNK; j >>= 1)
            bitonic_global_step<<<(N_IMG*SORT_N/2)/256, 256>>>(k, j);
        bitonic_local<<<128, 1024>>>(k, 0);
    }

    // top-3000 gather
    gather_kernel<<<(N_IMG*PRE_NMS + 255)/256, 256>>>();
    // IoU bitmask
    mask_kernel<<<dim3(47, 47, N_IMG), 64>>>();
    // sequential NMS scan -> rois
    scan_kernel<<<N_IMG, 32>>>(out);
}